// round 4
// baseline (speedup 1.0000x reference)
#include <cuda_runtime.h>

// AnchorLoss: sum over masked pairs of 1 - exp(-||(e_i+a_i)-(e_j+a_j)||^2 / 10)
// B=8, N=2048, D=2. Dominant cost: streaming the 134MB int32 mask once (~20us
// floor at achievable HBM BW).
//
// R4: cp.async 3-stage smem pipeline for the mask stream (fire-and-forget loads,
// deep outstanding queue) + persistent blocks with an atomic work queue (4096
// fine items) to kill the single-wave tail imbalance. Points (pre-scaled by
// sqrt(log2e/10)) staged in smem per batch; L2-resident so restaging is cheap.

#define BATCH      8
#define NPTS       2048
#define TI         8                        // rows per item
#define THREADS    128
#define NWARPS     4
#define CHUNK_COLS 128
#define CHUNKS     8                        // chunks per item (1024 cols)
#define COLS_PER_ITEM (CHUNKS * CHUNK_COLS)
#define ITEMS      (BATCH * (NPTS / TI) * 2)   // 4096
#define STAGES     3
#define STAGE_I4   (TI * CHUNK_COLS / 4)    // 256 int4 = 4KB per stage

__device__ unsigned int g_ctr;

__device__ __forceinline__ void cp_async16(void* dst, const void* src) {
    unsigned s = (unsigned)__cvta_generic_to_shared(dst);
    asm volatile("cp.async.cg.shared.global [%0], [%1], 16;" :: "r"(s), "l"(src));
}

__global__ __launch_bounds__(THREADS) void anchor_loss_kernel(
    const float* __restrict__ emb,
    const float* __restrict__ abscoords,
    const int*   __restrict__ mask,
    float*       __restrict__ out)
{
    __shared__ __align__(16) float2 c[NPTS];                    // 16KB scaled points
    __shared__ __align__(16) int4   mstage[STAGES][STAGE_I4];   // 12KB mask stages
    __shared__ float    wsum[NWARPS];
    __shared__ unsigned s_t;

    const int warp = threadIdx.x >> 5;
    const int lane = threadIdx.x & 31;
    const float S = 0.37982354f;   // sqrt(log2(e)/10): exp(-d2/10)=2^-((S dx)^2+(S dy)^2)

    float acc  = 0.0f;
    int   cur_b = -1;

    for (;;) {
        if (threadIdx.x == 0) s_t = atomicAdd(&g_ctr, 1u);
        __syncthreads();
        const unsigned t = s_t;
        if (t >= ITEMS) break;

        const int b  = (int)(t >> 9);                       // 512 items per batch
        const int i0 = (int)((t >> 1) & 255) * TI;
        const int j0 = (int)(t & 1) * COLS_PER_ITEM;

        if (b != cur_b) {
            const float2* e2 = (const float2*)emb       + (size_t)b * NPTS;
            const float2* a2 = (const float2*)abscoords + (size_t)b * NPTS;
            for (int j = threadIdx.x; j < NPTS; j += THREADS) {
                float2 e = e2[j], a = a2[j];
                c[j] = make_float2((e.x + a.x) * S, (e.y + a.y) * S);
            }
            cur_b = b;
            __syncthreads();
        }

        const float2 ciA = c[i0 + 2 * warp];
        const float2 ciB = c[i0 + 2 * warp + 1];

        const int* mrow0 = mask + ((size_t)b * NPTS + i0) * NPTS + j0;

        // ---- pipeline prologue: chunks 0,1 ----
        #pragma unroll
        for (int pu = 0; pu < 2; pu++) {
            #pragma unroll
            for (int k = 0; k < 2; k++) {
                int ci_ = threadIdx.x + 128 * k;
                int rr  = ci_ >> 5, off = ci_ & 31;
                cp_async16(&mstage[pu][ci_],
                           mrow0 + (size_t)rr * NPTS + pu * CHUNK_COLS + off * 4);
            }
            asm volatile("cp.async.commit_group;");
        }

        int   cnt = 0;
        float es  = 0.0f;

        #pragma unroll
        for (int u = 0; u < CHUNKS; u++) {
            if (u + 2 < CHUNKS) {
                #pragma unroll
                for (int k = 0; k < 2; k++) {
                    int ci_ = threadIdx.x + 128 * k;
                    int rr  = ci_ >> 5, off = ci_ & 31;
                    cp_async16(&mstage[(u + 2) % STAGES][ci_],
                               mrow0 + (size_t)rr * NPTS + (u + 2) * CHUNK_COLS + off * 4);
                }
            }
            asm volatile("cp.async.commit_group;");    // empty group when nothing issued
            asm volatile("cp.async.wait_group 2;");    // chunk u landed
            __syncthreads();

            const int4* ms = mstage[u % STAGES];
            const int4 ma = ms[(2 * warp)     * 32 + lane];
            const int4 mb = ms[(2 * warp + 1) * 32 + lane];
            const int jc = j0 + u * CHUNK_COLS + lane * 4;
            const float4 p0 = *reinterpret_cast<const float4*>(&c[jc]);
            const float4 p1 = *reinterpret_cast<const float4*>(&c[jc + 2]);

            float dx, dy, d2n, ev;

            // ---- row A ----
            dx = ciA.x - p0.x; dy = ciA.y - p0.y;
            d2n = fmaf(dx, -dx, dy * -dy);
            asm("ex2.approx.ftz.f32 %0, %1;" : "=f"(ev) : "f"(d2n));
            if (ma.x) es += ev;

            dx = ciA.x - p0.z; dy = ciA.y - p0.w;
            d2n = fmaf(dx, -dx, dy * -dy);
            asm("ex2.approx.ftz.f32 %0, %1;" : "=f"(ev) : "f"(d2n));
            if (ma.y) es += ev;

            dx = ciA.x - p1.x; dy = ciA.y - p1.y;
            d2n = fmaf(dx, -dx, dy * -dy);
            asm("ex2.approx.ftz.f32 %0, %1;" : "=f"(ev) : "f"(d2n));
            if (ma.z) es += ev;

            dx = ciA.x - p1.z; dy = ciA.y - p1.w;
            d2n = fmaf(dx, -dx, dy * -dy);
            asm("ex2.approx.ftz.f32 %0, %1;" : "=f"(ev) : "f"(d2n));
            if (ma.w) es += ev;

            // ---- row B (same points) ----
            dx = ciB.x - p0.x; dy = ciB.y - p0.y;
            d2n = fmaf(dx, -dx, dy * -dy);
            asm("ex2.approx.ftz.f32 %0, %1;" : "=f"(ev) : "f"(d2n));
            if (mb.x) es += ev;

            dx = ciB.x - p0.z; dy = ciB.y - p0.w;
            d2n = fmaf(dx, -dx, dy * -dy);
            asm("ex2.approx.ftz.f32 %0, %1;" : "=f"(ev) : "f"(d2n));
            if (mb.y) es += ev;

            dx = ciB.x - p1.x; dy = ciB.y - p1.y;
            d2n = fmaf(dx, -dx, dy * -dy);
            asm("ex2.approx.ftz.f32 %0, %1;" : "=f"(ev) : "f"(d2n));
            if (mb.z) es += ev;

            dx = ciB.x - p1.z; dy = ciB.y - p1.w;
            d2n = fmaf(dx, -dx, dy * -dy);
            asm("ex2.approx.ftz.f32 %0, %1;" : "=f"(ev) : "f"(d2n));
            if (mb.w) es += ev;

            cnt += (ma.x + ma.y) + (ma.z + ma.w)
                 + (mb.x + mb.y) + (mb.z + mb.w);   // mask values are 0/1

            __syncthreads();   // stage reuse fence (next iter overwrites u-1's stage)
        }

        acc += (float)cnt - es;   // masked sum of (1 - e)
    }

    asm volatile("cp.async.wait_group 0;");

    #pragma unroll
    for (int off = 16; off; off >>= 1)
        acc += __shfl_xor_sync(0xffffffffu, acc, off);
    if (lane == 0) wsum[warp] = acc;
    __syncthreads();

    if (threadIdx.x == 0) {
        float s = 0.0f;
        #pragma unroll
        for (int w = 0; w < NWARPS; w++) s += wsum[w];
        atomicAdd(out, s);
    }
}

extern "C" void kernel_launch(void* const* d_in, const int* in_sizes, int n_in,
                              void* d_out, int out_size)
{
    const float* emb  = (const float*)d_in[0];
    const float* absc = (const float*)d_in[1];
    const int*   mask = (const int*)d_in[2];
    float*       out  = (float*)d_out;

    void* ctr_addr = nullptr;
    cudaGetSymbolAddress(&ctr_addr, g_ctr);
    cudaMemsetAsync(ctr_addr, 0, sizeof(unsigned int));
    cudaMemsetAsync(out, 0, sizeof(float));

    dim3 grid(8 * 148);   // persistent: ~8 CTAs/SM, work-stealing via g_ctr
    anchor_loss_kernel<<<grid, THREADS>>>(emb, absc, mask, out);
}

// round 5
// speedup vs baseline: 1.0604x; 1.0604x over previous
#include <cuda_runtime.h>

// AnchorLoss: sum over masked pairs of 1 - exp(-||(e_i+a_i)-(e_j+a_j)||^2 / 10)
// B=8, N=2048, D=2. Dominant cost: streaming the 134MB int32 mask once.
//
// R5: back to register-resident mask streams (R4's smem staging was pure
// overhead). Fixes vs R3:
//  - one row per warp with a depth-4 rotating prefetch ring -> 4 LDG.128
//    continuously in flight per warp (no consume-all convoy point)
//  - persistent CTAs + atomic work queue (4096 items) -> no static-wave tail
//  - __launch_bounds__(128,10): ~40 warps/SM resident

#define BATCH    8
#define NPTS     2048
#define TI       4                      // rows per item (1 per warp)
#define THREADS  128
#define NWARPS   4
#define NITER    (NPTS/4/32)            // 16 int4-chunks per lane per row
#define DEPTH    4                      // prefetch ring depth
#define ITEMS    (BATCH * (NPTS / TI))  // 4096

__device__ unsigned int g_ctr;

__global__ void __launch_bounds__(THREADS, 10) anchor_loss_kernel(
    const float* __restrict__ emb,
    const float* __restrict__ abscoords,
    const int*   __restrict__ mask,
    float*       __restrict__ out)
{
    __shared__ __align__(16) float2 c[NPTS];   // 16KB scaled points (per batch)
    __shared__ float    wsum[NWARPS];
    __shared__ unsigned s_t;

    const int warp = threadIdx.x >> 5;
    const int lane = threadIdx.x & 31;
    const float S = 0.37982354f;   // sqrt(log2(e)/10): exp(-d2/10)=2^-((S dx)^2+(S dy)^2)

    float acc   = 0.0f;
    int   cur_b = -1;

    for (;;) {
        if (threadIdx.x == 0) s_t = atomicAdd(&g_ctr, 1u);
        __syncthreads();
        const unsigned t = s_t;
        if (t >= ITEMS) break;

        const int b  = (int)(t >> 9);              // 512 items per batch
        const int i0 = (int)(t & 511) * TI;        // 4 adjacent rows

        if (b != cur_b) {
            const float2* e2 = (const float2*)emb       + (size_t)b * NPTS;
            const float2* a2 = (const float2*)abscoords + (size_t)b * NPTS;
            for (int j = threadIdx.x; j < NPTS; j += THREADS) {
                float2 e = e2[j], a = a2[j];
                c[j] = make_float2((e.x + a.x) * S, (e.y + a.y) * S);
            }
            cur_b = b;
            __syncthreads();
        }

        const int    i  = i0 + warp;               // this warp's row
        const float2 ci = c[i];
        const float  cx = ci.x, cy = ci.y;

        const int4* mrow = reinterpret_cast<const int4*>(
            mask + ((size_t)b * NPTS + i) * NPTS) + lane;
        const float4* c4 = reinterpret_cast<const float4*>(c) + 2 * lane;

        // prologue: fill the ring with chunks 0..3
        int4 mbuf[DEPTH];
        #pragma unroll
        for (int d = 0; d < DEPTH; d++)
            mbuf[d] = __ldcs(mrow + 32 * d);

        float es  = 0.0f;
        int   cnt = 0;

        #pragma unroll
        for (int u = 0; u < NITER; u++) {
            const int4 m = mbuf[u & (DEPTH - 1)];

            // refill this slot with chunk u+4 (wraps in-bounds on the tail;
            // wrapped results are never consumed)
            mbuf[u & (DEPTH - 1)] = __ldcs(mrow + 32 * ((u + DEPTH) & (NITER - 1)));

            const float4 p0 = c4[64 * u];          // points 4u..4u+1 (scaled)
            const float4 p1 = c4[64 * u + 1];      // points 4u+2..4u+3

            float dx, dy, d2n, ev;

            dx = cx - p0.x; dy = cy - p0.y;
            d2n = fmaf(dx, -dx, dy * -dy);
            asm("ex2.approx.ftz.f32 %0, %1;" : "=f"(ev) : "f"(d2n));
            if (m.x) es += ev;

            dx = cx - p0.z; dy = cy - p0.w;
            d2n = fmaf(dx, -dx, dy * -dy);
            asm("ex2.approx.ftz.f32 %0, %1;" : "=f"(ev) : "f"(d2n));
            if (m.y) es += ev;

            dx = cx - p1.x; dy = cy - p1.y;
            d2n = fmaf(dx, -dx, dy * -dy);
            asm("ex2.approx.ftz.f32 %0, %1;" : "=f"(ev) : "f"(d2n));
            if (m.z) es += ev;

            dx = cx - p1.z; dy = cy - p1.w;
            d2n = fmaf(dx, -dx, dy * -dy);
            asm("ex2.approx.ftz.f32 %0, %1;" : "=f"(ev) : "f"(d2n));
            if (m.w) es += ev;

            cnt += (m.x + m.y) + (m.z + m.w);      // mask values are 0/1
        }

        acc += (float)cnt - es;                    // masked sum of (1 - e)
    }

    #pragma unroll
    for (int off = 16; off; off >>= 1)
        acc += __shfl_xor_sync(0xffffffffu, acc, off);
    if (lane == 0) wsum[warp] = acc;
    __syncthreads();

    if (threadIdx.x == 0) {
        float s = 0.0f;
        #pragma unroll
        for (int w = 0; w < NWARPS; w++) s += wsum[w];
        atomicAdd(out, s);
    }
}

extern "C" void kernel_launch(void* const* d_in, const int* in_sizes, int n_in,
                              void* d_out, int out_size)
{
    const float* emb  = (const float*)d_in[0];
    const float* absc = (const float*)d_in[1];
    const int*   mask = (const int*)d_in[2];
    float*       out  = (float*)d_out;

    void* ctr_addr = nullptr;
    cudaGetSymbolAddress(&ctr_addr, g_ctr);
    cudaMemsetAsync(ctr_addr, 0, sizeof(unsigned int));
    cudaMemsetAsync(out, 0, sizeof(float));

    dim3 grid(10 * 148);   // persistent workers; work-stealing via g_ctr
    anchor_loss_kernel<<<grid, THREADS>>>(emb, absc, mask, out);
}

// round 8
// speedup vs baseline: 1.2489x; 1.1778x over previous
#include <cuda_runtime.h>

// AnchorLoss: sum over masked pairs of 1 - exp(-||(e_i+a_i)-(e_j+a_j)||^2 / 10)
// B=8, N=2048, D=2. Mandatory traffic: the 134MB int32 mask, read once.
//
// R8: same theory as R6/R7 (kill the L1 crossbar cost of per-pair point LDS),
// de-risked after two infra failures: no device globals, no persistent loop,
// no smem staging, no inner barriers. Static grid of 4096 one-item blocks.
//   item = 128-col slab x 64 rows:
//     - lane's 4 slab points: computed once from gmem (L2-resident) into regs
//     - per row: 1 coalesced mask LDG.128 + warp-uniform point load, both in a
//       depth-4 register prefetch ring (continuous MLP, no convoy)
//   exp(-d2/10) = ex2(-(S dx)^2 - (S dy)^2), S = sqrt(log2(e)/10).
//   masked sum of (1 - e) accumulated as (count - sum_e).

#define BATCH    8
#define NPTS     2048
#define THREADS  128
#define NWARPS   4
#define ROWS_IT  64                      // rows per item/block
#define ROWS_PW  16                      // rows per warp
#define DEPTH    4

__global__ void __launch_bounds__(THREADS, 8) anchor_loss_kernel(
    const float* __restrict__ emb,
    const float* __restrict__ abscoords,
    const int*   __restrict__ mask,
    float*       __restrict__ out)
{
    __shared__ float wsum[NWARPS];

    const int warp = threadIdx.x >> 5;
    const int lane = threadIdx.x & 31;
    const float S = 0.37982354f;         // sqrt(log2(e)/10)

    // item decomposition: 4096 blocks = 8 batches * 16 slabs * 32 row-groups
    const int b   = blockIdx.x >> 9;             // 512 items per batch
    const int rem = blockIdx.x & 511;
    const int j0  = (rem >> 5) * 128;            // column slab base
    const int i0  = (rem & 31) * ROWS_IT;        // row-group base

    const float2* e2 = (const float2*)emb       + (size_t)b * NPTS;
    const float2* a2 = (const float2*)abscoords + (size_t)b * NPTS;

    // Lane's 4 slab points -> registers (coalesced; emb/abs are L2-resident).
    const float4* ee = reinterpret_cast<const float4*>(e2 + j0);
    const float4* aa = reinterpret_cast<const float4*>(a2 + j0);
    float4 p0, p1;
    {
        float4 ex0 = __ldg(ee + 2 * lane);
        float4 ex1 = __ldg(ee + 2 * lane + 1);
        float4 ax0 = __ldg(aa + 2 * lane);
        float4 ax1 = __ldg(aa + 2 * lane + 1);
        p0 = make_float4((ex0.x + ax0.x) * S, (ex0.y + ax0.y) * S,
                         (ex0.z + ax0.z) * S, (ex0.w + ax0.w) * S);
        p1 = make_float4((ex1.x + ax1.x) * S, (ex1.y + ax1.y) * S,
                         (ex1.z + ax1.z) * S, (ex1.w + ax1.w) * S);
    }

    const int iA = i0 + warp * ROWS_PW;          // this warp's 16 rows
    const int4* mrow = reinterpret_cast<const int4*>(
        mask + ((size_t)b * NPTS + iA) * NPTS + j0) + lane;
    // row stride = NPTS ints = 512 int4

    // depth-4 prefetch rings: mask chunk + row point (warp-uniform load)
    int4   mb[DEPTH];
    float2 rp[DEPTH];
    #pragma unroll
    for (int d = 0; d < DEPTH; d++) {
        mb[d] = __ldcs(mrow + 512 * d);
        float2 er = __ldg(e2 + iA + d);
        float2 ar = __ldg(a2 + iA + d);
        rp[d] = make_float2((er.x + ar.x) * S, (er.y + ar.y) * S);
    }

    float es  = 0.0f;
    int   cnt = 0;

    #pragma unroll
    for (int r = 0; r < ROWS_PW; r++) {
        const int4   m  = mb[r & (DEPTH - 1)];
        const float2 ci = rp[r & (DEPTH - 1)];

        // refill slot with row r+4 (wraps in-bounds on tail; discarded)
        const int rn = (r + DEPTH) & (ROWS_PW - 1);
        mb[r & (DEPTH - 1)] = __ldcs(mrow + 512 * rn);
        {
            float2 er = __ldg(e2 + iA + rn);
            float2 ar = __ldg(a2 + iA + rn);
            rp[r & (DEPTH - 1)] = make_float2((er.x + ar.x) * S, (er.y + ar.y) * S);
        }

        const float cx = ci.x, cy = ci.y;
        float dx, dy, d2n, ev;

        dx = cx - p0.x; dy = cy - p0.y;
        d2n = fmaf(dx, -dx, dy * -dy);
        asm("ex2.approx.ftz.f32 %0, %1;" : "=f"(ev) : "f"(d2n));
        if (m.x) es += ev;

        dx = cx - p0.z; dy = cy - p0.w;
        d2n = fmaf(dx, -dx, dy * -dy);
        asm("ex2.approx.ftz.f32 %0, %1;" : "=f"(ev) : "f"(d2n));
        if (m.y) es += ev;

        dx = cx - p1.x; dy = cy - p1.y;
        d2n = fmaf(dx, -dx, dy * -dy);
        asm("ex2.approx.ftz.f32 %0, %1;" : "=f"(ev) : "f"(d2n));
        if (m.z) es += ev;

        dx = cx - p1.z; dy = cy - p1.w;
        d2n = fmaf(dx, -dx, dy * -dy);
        asm("ex2.approx.ftz.f32 %0, %1;" : "=f"(ev) : "f"(d2n));
        if (m.w) es += ev;

        cnt += (m.x + m.y) + (m.z + m.w);        // mask values are 0/1
    }

    float acc = (float)cnt - es;                 // masked sum of (1 - e)

    #pragma unroll
    for (int off = 16; off; off >>= 1)
        acc += __shfl_xor_sync(0xffffffffu, acc, off);
    if (lane == 0) wsum[warp] = acc;
    __syncthreads();

    if (threadIdx.x == 0) {
        float s = 0.0f;
        #pragma unroll
        for (int w = 0; w < NWARPS; w++) s += wsum[w];
        atomicAdd(out, s);
    }
}

extern "C" void kernel_launch(void* const* d_in, const int* in_sizes, int n_in,
                              void* d_out, int out_size)
{
    const float* emb  = (const float*)d_in[0];
    const float* absc = (const float*)d_in[1];
    const int*   mask = (const int*)d_in[2];
    float*       out  = (float*)d_out;

    cudaMemsetAsync(out, 0, sizeof(float));

    dim3 grid(BATCH * 512);   // 4096 one-item blocks (~2.8 waves @ 8 CTA/SM)
    anchor_loss_kernel<<<grid, THREADS>>>(emb, absc, mask, out);
}

// round 11
// speedup vs baseline: 1.3758x; 1.1016x over previous
#include <cuda_runtime.h>

// AnchorLoss: sum over masked pairs of 1 - exp(-||(e_i+a_i)-(e_j+a_j)||^2 / 10)
// B=8, N=2048, D=2. Mandatory traffic: the 134MB int32 mask, read once.
//
// R10 == R9 resubmission (R9 bench was an infra failure, never measured).
// Cut the issue stream (R8: issue 64.4% co-limited with DRAM 63%).
//  - Kernel expansion: exponent = w_r + w_c + 2u_r*u_c + 2v_r*v_c with
//    u=S*x, v=S*y, w=-(u^2+v^2). Pair = FFMA,FFMA,MUFU,ISETP,@P FADD (5 instr);
//    2^(w_r) factored out per row (one FFMA scales the row partial sum).
//  - Row constants (2u, 2v, 2^w) built ONCE per item by lanes 0..7 and fetched
//    per row with 3 SHFL.IDX — no per-row LDG/FP rebuild, no rp ring.
//  - Items 32 rows x 128 cols (grid 8192) -> ~4us CTAs, smaller ragged tail.
//  - Mask: depth-4 register LDG.128 ring (continuous MLP), __ldcs streaming.

#define BATCH    8
#define NPTS     2048
#define THREADS  128
#define NWARPS   4
#define ROWS_IT  32                      // rows per item/block
#define ROWS_PW  8                       // rows per warp
#define DEPTH    4

__global__ void __launch_bounds__(THREADS, 9) anchor_loss_kernel(
    const float* __restrict__ emb,
    const float* __restrict__ abscoords,
    const int*   __restrict__ mask,
    float*       __restrict__ out)
{
    __shared__ float wsum[NWARPS];

    const int warp = threadIdx.x >> 5;
    const int lane = threadIdx.x & 31;
    const float S = 0.37982354f;         // sqrt(log2(e)/10)

    // 8192 blocks = 8 batches * 16 slabs * 64 row-groups
    const int b   = blockIdx.x >> 10;            // 1024 items per batch
    const int rem = blockIdx.x & 1023;
    const int j0  = (rem >> 6) * 128;            // column slab base
    const int i0  = (rem & 63) * ROWS_IT;        // row-group base

    const float2* e2 = (const float2*)emb       + (size_t)b * NPTS;
    const float2* a2 = (const float2*)abscoords + (size_t)b * NPTS;

    // ---- lane's 4 slab-point constants (u, v, w = -(u^2+v^2)) ----
    float u4[4], v4[4], w4[4];
    {
        const float4* ee = reinterpret_cast<const float4*>(e2 + j0);
        const float4* aa = reinterpret_cast<const float4*>(a2 + j0);
        float4 ex0 = __ldg(ee + 2 * lane);
        float4 ex1 = __ldg(ee + 2 * lane + 1);
        float4 ax0 = __ldg(aa + 2 * lane);
        float4 ax1 = __ldg(aa + 2 * lane + 1);
        u4[0] = (ex0.x + ax0.x) * S;  v4[0] = (ex0.y + ax0.y) * S;
        u4[1] = (ex0.z + ax0.z) * S;  v4[1] = (ex0.w + ax0.w) * S;
        u4[2] = (ex1.x + ax1.x) * S;  v4[2] = (ex1.y + ax1.y) * S;
        u4[3] = (ex1.z + ax1.z) * S;  v4[3] = (ex1.w + ax1.w) * S;
        #pragma unroll
        for (int k = 0; k < 4; k++)
            w4[k] = -fmaf(u4[k], u4[k], v4[k] * v4[k]);
    }

    // ---- this warp's 8 row constants, one per lane (lanes 0..7; others dup) ----
    const int iA = i0 + warp * ROWS_PW;
    float ru2, rv2, rew;
    {
        const int rl = iA + (lane & (ROWS_PW - 1));
        float2 er = __ldg(e2 + rl);
        float2 ar = __ldg(a2 + rl);
        float u = (er.x + ar.x) * S;
        float v = (er.y + ar.y) * S;
        ru2 = u + u;
        rv2 = v + v;
        float w = -fmaf(u, u, v * v);
        asm("ex2.approx.ftz.f32 %0, %1;" : "=f"(rew) : "f"(w));   // 2^(w_r)
    }

    const int4* mrow = reinterpret_cast<const int4*>(
        mask + ((size_t)b * NPTS + iA) * NPTS + j0) + lane;
    // row stride = NPTS ints = 512 int4

    // depth-4 mask prefetch ring
    int4 mb[DEPTH];
    #pragma unroll
    for (int d = 0; d < DEPTH; d++)
        mb[d] = __ldcs(mrow + 512 * d);

    float es  = 0.0f;
    int   cnt = 0;

    #pragma unroll
    for (int r = 0; r < ROWS_PW; r++) {
        const int4 m = mb[r & (DEPTH - 1)];
        // refill slot with row r+4 (wraps in-bounds on tail; discarded)
        mb[r & (DEPTH - 1)] = __ldcs(mrow + 512 * ((r + DEPTH) & (ROWS_PW - 1)));

        // fetch row constants from the owning lane
        const float u2r = __shfl_sync(0xffffffffu, ru2, r);
        const float v2r = __shfl_sync(0xffffffffu, rv2, r);
        const float ewr = __shfl_sync(0xffffffffu, rew, r);

        float racc = 0.0f;
        float t, ev;

        t = fmaf(u2r, u4[0], w4[0]);
        t = fmaf(v2r, v4[0], t);
        asm("ex2.approx.ftz.f32 %0, %1;" : "=f"(ev) : "f"(t));
        if (m.x) racc += ev;

        t = fmaf(u2r, u4[1], w4[1]);
        t = fmaf(v2r, v4[1], t);
        asm("ex2.approx.ftz.f32 %0, %1;" : "=f"(ev) : "f"(t));
        if (m.y) racc += ev;

        t = fmaf(u2r, u4[2], w4[2]);
        t = fmaf(v2r, v4[2], t);
        asm("ex2.approx.ftz.f32 %0, %1;" : "=f"(ev) : "f"(t));
        if (m.z) racc += ev;

        t = fmaf(u2r, u4[3], w4[3]);
        t = fmaf(v2r, v4[3], t);
        asm("ex2.approx.ftz.f32 %0, %1;" : "=f"(ev) : "f"(t));
        if (m.w) racc += ev;

        es = fmaf(racc, ewr, es);            // row partial * 2^(w_r)
        cnt += (m.x + m.y) + (m.z + m.w);    // mask values are 0/1
    }

    float acc = (float)cnt - es;             // masked sum of (1 - e)

    #pragma unroll
    for (int off = 16; off; off >>= 1)
        acc += __shfl_xor_sync(0xffffffffu, acc, off);
    if (lane == 0) wsum[warp] = acc;
    __syncthreads();

    if (threadIdx.x == 0) {
        float s = 0.0f;
        #pragma unroll
        for (int w = 0; w < NWARPS; w++) s += wsum[w];
        atomicAdd(out, s);
    }
}

extern "C" void kernel_launch(void* const* d_in, const int* in_sizes, int n_in,
                              void* d_out, int out_size)
{
    const float* emb  = (const float*)d_in[0];
    const float* absc = (const float*)d_in[1];
    const int*   mask = (const int*)d_in[2];
    float*       out  = (float*)d_out;

    cudaMemsetAsync(out, 0, sizeof(float));

    dim3 grid(BATCH * 1024);   // 8192 one-item blocks
    anchor_loss_kernel<<<grid, THREADS>>>(emb, absc, mask, out);
}